// round 1
// baseline (speedup 1.0000x reference)
#include <cuda_runtime.h>
#include <math.h>

typedef unsigned long long ull;

#define DINL __device__ __forceinline__

DINL ull pk2(float lo, float hi) {
    ull r; asm("mov.b64 %0, {%1,%2};" : "=l"(r) : "f"(lo), "f"(hi)); return r;
}
DINL void upk2(ull v, float& lo, float& hi) {
    asm("mov.b64 {%0,%1}, %2;" : "=f"(lo), "=f"(hi) : "l"(v));
}
DINL ull ffma2(ull a, ull b, ull c) {
    ull d; asm("fma.rn.f32x2 %0, %1, %2, %3;" : "=l"(d) : "l"(a), "l"(b), "l"(c)); return d;
}
DINL float ex2f(float x) {
    float y; asm("ex2.approx.f32 %0, %1;" : "=f"(y) : "f"(x)); return y;
}
DINL float gelu_exact(float x) {
    return 0.5f * x * (1.0f + erff(x * 0.7071067811865476f));
}

constexpr int B  = 2;
constexpr int C  = 64;
constexpr int HW = 48;
constexpr int N  = 2304;   // 48*48
constexpr int H  = 8;      // heads
constexpr int D  = 8;      // head dim

// ---------------- scratch (device globals; no allocs allowed) ----------------
__device__ __align__(16) float g_dep_t[B * C * N];            // (b, c, n)  n = w*48 + h
__device__ __align__(16) float g_qkv[2][3][B * H * N * D];    // [stream rgb=0/dep=1][q,k,v] (b,h,n,d)
__device__ __align__(16) float g_att[2][B * N * C];           // attention outputs (b,n,c)
__device__ __align__(16) float g_wefft[2][C * C];             // effective weights, [k][o] layout
__device__ __align__(16) float g_beff[C];                     // effective bias

// ---------------- kernel 1: depth 1x1 conv + ReLU + bilinear x2 upsample ----------------
// dep_t[b][c][n] with n = w*48 + h ; upsample half-pixel convention (matches jax bilinear x2)
__global__ void k_depth(const float* __restrict__ depth,
                        const float* __restrict__ w_exp,
                        const float* __restrict__ b_exp) {
    int idx = blockIdx.x * 256 + threadIdx.x;   // 0 .. B*N-1
    if (idx >= B * N) return;
    int b = idx / N, n = idx % N;
    int w = n / HW, h = n % HW;

    float sy = h * 0.5f - 0.25f;
    float fy = floorf(sy);
    float wy1 = sy - fy, wy0 = 1.0f - wy1;
    int y0 = max((int)fy, 0), y1 = min((int)fy + 1, 23);

    float sx = w * 0.5f - 0.25f;
    float fx = floorf(sx);
    float wx1 = sx - fx, wx0 = 1.0f - wx1;
    int x0 = max((int)fx, 0), x1 = min((int)fx + 1, 23);

    const float* dp = depth + b * 576;
    float d00 = dp[y0 * 24 + x0], d01 = dp[y0 * 24 + x1];
    float d10 = dp[y1 * 24 + x0], d11 = dp[y1 * 24 + x1];
    float w00 = wy0 * wx0, w01 = wy0 * wx1, w10 = wy1 * wx0, w11 = wy1 * wx1;

    for (int c = 0; c < C; c++) {
        float we = w_exp[c], be = b_exp[c];
        float v = w00 * fmaxf(fmaf(we, d00, be), 0.f)
                + w01 * fmaxf(fmaf(we, d01, be), 0.f)
                + w10 * fmaxf(fmaf(we, d10, be), 0.f)
                + w11 * fmaxf(fmaf(we, d11, be), 0.f);
        g_dep_t[(b * C + c) * N + n] = v;
    }
}

// ---------------- kernel 2: fused QKV GEMMs (both streams) ----------------
// block = one (stream, b, w-column): 48 rows x 192 output channels, K=64
__global__ void k_qkv(const float* __restrict__ rgb,
                      const float* __restrict__ wq0, const float* __restrict__ wk0, const float* __restrict__ wv0,
                      const float* __restrict__ wq1, const float* __restrict__ wk1, const float* __restrict__ wv1) {
    extern __shared__ float sm[];
    float* sX  = sm;                 // [c][h] stride 49
    float* sWt = sm + 64 * 49;       // [c][oc] stride 196 (16B aligned rows)

    int w = blockIdx.x, b = blockIdx.y, s = blockIdx.z;
    int tid = threadIdx.x;           // 288 threads

    for (int idx = tid; idx < 64 * 48; idx += 288) {
        int c = idx / 48, h = idx % 48;
        float v = (s == 0) ? rgb[(b * C + c) * N + h * HW + w]
                           : g_dep_t[(b * C + c) * N + w * HW + h];
        sX[c * 49 + h] = v;
    }
    const float* wq = s ? wq1 : wq0;
    const float* wk = s ? wk1 : wk0;
    const float* wv = s ? wv1 : wv0;
    for (int idx = tid; idx < 64 * 192; idx += 288) {
        int oc = idx / 64, c = idx % 64;
        int sel = oc >> 6, ocm = oc & 63;
        const float* wm = (sel == 0) ? wq : (sel == 1 ? wk : wv);
        sWt[c * 196 + oc] = wm[ocm * 64 + c];
    }
    __syncthreads();

    int nl = tid % 48;        // = h
    int g  = tid / 48;        // 0..5
    int oc0 = g * 32;

    ull acc[16];
#pragma unroll
    for (int j = 0; j < 16; j++) acc[j] = 0ull;

    for (int c = 0; c < 64; c++) {
        float xv = sX[c * 49 + nl];
        ull xp = pk2(xv, xv);
        const ulonglong2* w2 = (const ulonglong2*)(sWt + c * 196 + oc0);
#pragma unroll
        for (int j = 0; j < 8; j++) {
            ulonglong2 wv2 = w2[j];
            acc[2 * j]     = ffma2(xp, wv2.x, acc[2 * j]);
            acc[2 * j + 1] = ffma2(xp, wv2.y, acc[2 * j + 1]);
        }
    }

    int n = w * HW + nl;
#pragma unroll
    for (int j = 0; j < 16; j++) {
        int oc = oc0 + 2 * j;
        int mat = oc >> 6, ocm = oc & 63, hd = ocm >> 3, d = ocm & 7;
        float lo, hi; upk2(acc[j], lo, hi);
        *(float2*)&g_qkv[s][mat][((size_t)(b * H + hd) * N + n) * D + d] = make_float2(lo, hi);
    }
}

// ---------------- kernel 3: cross-attention (flash-style, fixed-shift softmax) ----------------
// grid: x = q-chunk (9), y = head (8), z = att*2 + b (4). block 256, 1 query/thread.
__global__ void k_attn() {
    extern __shared__ float sm[];
    int chunk = blockIdx.x, hd = blockIdx.y, z = blockIdx.z;
    int att = z >> 1, b = z & 1;
    int tid = threadIdx.x;

    const float4* Kg = (const float4*)(g_qkv[1 - att][1] + (size_t)(b * H + hd) * N * D);
    const float4* Vg = (const float4*)(g_qkv[1 - att][2] + (size_t)(b * H + hd) * N * D);
    float4* sK = (float4*)sm;
    float4* sV = sK + N * 2;
    for (int i = tid; i < N * 2; i += 256) {
        sK[i] = Kg[i];
        sV[i] = Vg[i];
    }
    __syncthreads();

    int n = chunk * 256 + tid;
    const float* qp = g_qkv[att][0] + ((size_t)(b * H + hd) * N + n) * D;
    // fold scale (1/sqrt(8)) and log2(e) into Q; fold constant shift into dot init
    constexpr float QS = 0.3535533905932738f * 1.4426950408889634f;
    float4 qa = ((const float4*)qp)[0];
    float4 qb = ((const float4*)qp)[1];
    ull q0 = pk2(qa.x * QS, qa.y * QS);
    ull q1 = pk2(qa.z * QS, qa.w * QS);
    ull q2 = pk2(qb.x * QS, qb.y * QS);
    ull q3 = pk2(qb.z * QS, qb.w * QS);
    const ull SHIFT = pk2(-14.4269504f, 0.0f);   // exp(-10) shift, cancels in normalization

    const ulonglong2* sKu = (const ulonglong2*)sK;
    const ulonglong2* sVu = (const ulonglong2*)sV;

    ull a0 = 0, a1 = 0, a2 = 0, a3 = 0;
    float ssum = 0.0f;

#pragma unroll 4
    for (int m = 0; m < N; m++) {
        ulonglong2 ka = sKu[2 * m], kb = sKu[2 * m + 1];
        ull dt = ffma2(q0, ka.x, SHIFT);
        dt = ffma2(q1, ka.y, dt);
        dt = ffma2(q2, kb.x, dt);
        dt = ffma2(q3, kb.y, dt);
        float lo, hi; upk2(dt, lo, hi);
        float p = ex2f(lo + hi);
        ssum += p;
        ull pp = pk2(p, p);
        ulonglong2 va = sVu[2 * m], vb = sVu[2 * m + 1];
        a0 = ffma2(pp, va.x, a0);
        a1 = ffma2(pp, va.y, a1);
        a2 = ffma2(pp, vb.x, a2);
        a3 = ffma2(pp, vb.y, a3);
    }

    float inv = 1.0f / ssum;
    float o[8];
    upk2(a0, o[0], o[1]); upk2(a1, o[2], o[3]);
    upk2(a2, o[4], o[5]); upk2(a3, o[6], o[7]);
    float* op = g_att[att] + ((size_t)(b * N + n)) * C + hd * D;
    ((float4*)op)[0] = make_float4(o[0] * inv, o[1] * inv, o[2] * inv, o[3] * inv);
    ((float4*)op)[1] = make_float4(o[4] * inv, o[5] * inv, o[6] * inv, o[7] * inv);
}

// ---------------- kernel 4: precompute effective proj+compress weights ----------------
// Weff_att[k][o] = sum_c w_comp[o][att*64+c] * w_proj[c][k]
// beff[o] = b_comp[o] + sum_c w_comp[o][c]*b_rgb_proj[c] + w_comp[o][64+c]*b_dep_proj[c]
__global__ void k_weff(const float* __restrict__ wrp, const float* __restrict__ brp,
                       const float* __restrict__ wdp, const float* __restrict__ bdp,
                       const float* __restrict__ wcomp, const float* __restrict__ bcomp) {
    int tid = threadIdx.x;   // 256
    for (int idx = tid; idx < 8192; idx += 256) {
        int att = idx >> 12, rem = idx & 4095, k = rem >> 6, o = rem & 63;
        const float* wp = att ? wdp : wrp;
        float acc = 0.0f;
        for (int c = 0; c < 64; c++)
            acc = fmaf(wcomp[o * 128 + att * 64 + c], wp[c * 64 + k], acc);
        g_wefft[att][k * 64 + o] = acc;
    }
    if (tid < 64) {
        float acc = bcomp[tid];
        for (int c = 0; c < 64; c++) {
            acc = fmaf(wcomp[tid * 128 + c], brp[c], acc);
            acc = fmaf(wcomp[tid * 128 + 64 + c], bdp[c], acc);
        }
        g_beff[tid] = acc;
    }
}

// ---------------- kernel 5: fused (proj + compress) GEMM + GELU ----------------
// out[b][o][n] = gelu( sum_k A0[b,n,k]*W0t[k,o] + A1[b,n,k]*W1t[k,o] + beff[o] )
__global__ void k_out(float* __restrict__ out) {
    extern __shared__ float sm[];
    float* sA1 = sm;                  // [64 rows][65]
    float* sA2 = sm + 64 * 65;
    float* sW  = sm + 2 * 64 * 65;    // 2 mats [k][o], 4096 each
    float* sB  = sW + 2 * 64 * 64;

    int n0 = blockIdx.x * 64;         // global row over B*N = 4608
    int tid = threadIdx.x;            // 256

    for (int idx = tid; idx < 64 * 64; idx += 256) {
        int r = idx >> 6, k = idx & 63;
        sA1[r * 65 + k] = g_att[0][(size_t)(n0 + r) * C + k];
        sA2[r * 65 + k] = g_att[1][(size_t)(n0 + r) * C + k];
    }
    for (int idx = tid; idx < 2 * 64 * 64; idx += 256)
        sW[idx] = ((const float*)g_wefft)[idx];
    if (tid < 64) sB[tid] = g_beff[tid];
    __syncthreads();

    int r = tid & 63, og = tid >> 6, o0 = og * 16;
    ull acc[8];
#pragma unroll
    for (int j = 0; j < 8; j++) acc[j] = 0ull;

    for (int k = 0; k < 64; k++) {
        float av1 = sA1[r * 65 + k];
        float av2 = sA2[r * 65 + k];
        ull p1 = pk2(av1, av1), p2 = pk2(av2, av2);
        const ulonglong2* w1 = (const ulonglong2*)(sW + k * 64 + o0);
        const ulonglong2* w2 = (const ulonglong2*)(sW + 4096 + k * 64 + o0);
#pragma unroll
        for (int j = 0; j < 4; j++) {
            ulonglong2 u1 = w1[j], u2 = w2[j];
            acc[2 * j]     = ffma2(p1, u1.x, acc[2 * j]);
            acc[2 * j]     = ffma2(p2, u2.x, acc[2 * j]);
            acc[2 * j + 1] = ffma2(p1, u1.y, acc[2 * j + 1]);
            acc[2 * j + 1] = ffma2(p2, u2.y, acc[2 * j + 1]);
        }
    }

    int b = (n0 >= N) ? 1 : 0;
    int n = n0 - b * N + r;
#pragma unroll
    for (int j = 0; j < 8; j++) {
        float lo, hi; upk2(acc[j], lo, hi);
        int o = o0 + 2 * j;
        out[((size_t)(b * C + o)) * N + n]     = gelu_exact(lo + sB[o]);
        out[((size_t)(b * C + o + 1)) * N + n] = gelu_exact(hi + sB[o + 1]);
    }
}

// ---------------- launch ----------------
extern "C" void kernel_launch(void* const* d_in, const int* in_sizes, int n_in,
                              void* d_out, int out_size) {
    const float* rgb    = (const float*)d_in[0];
    const float* depth  = (const float*)d_in[1];
    const float* w_exp  = (const float*)d_in[2];
    const float* b_exp  = (const float*)d_in[3];
    const float* wrq    = (const float*)d_in[4];
    const float* wrk    = (const float*)d_in[5];
    const float* wrv    = (const float*)d_in[6];
    const float* wdq    = (const float*)d_in[7];
    const float* wdk    = (const float*)d_in[8];
    const float* wdv    = (const float*)d_in[9];
    const float* wrp    = (const float*)d_in[10];
    const float* brp    = (const float*)d_in[11];
    const float* wdp    = (const float*)d_in[12];
    const float* bdp    = (const float*)d_in[13];
    const float* wcomp  = (const float*)d_in[14];
    const float* bcomp  = (const float*)d_in[15];

    static bool attr_done = false;
    if (!attr_done) {
        cudaFuncSetAttribute(k_qkv,  cudaFuncAttributeMaxDynamicSharedMemorySize, (64*49 + 64*196) * 4);
        cudaFuncSetAttribute(k_attn, cudaFuncAttributeMaxDynamicSharedMemorySize, 2 * N * D * 4);
        cudaFuncSetAttribute(k_out,  cudaFuncAttributeMaxDynamicSharedMemorySize, (2*64*65 + 2*64*64 + 64) * 4);
        attr_done = true;
    }

    k_weff<<<1, 256>>>(wrp, brp, wdp, bdp, wcomp, bcomp);
    k_depth<<<(B * N + 255) / 256, 256>>>(depth, w_exp, b_exp);
    k_qkv<<<dim3(48, 2, 2), 288, (64*49 + 64*196) * 4>>>(rgb, wrq, wrk, wrv, wdq, wdk, wdv);
    k_attn<<<dim3(9, 8, 4), 256, 2 * N * D * 4>>>();
    k_out<<<(B * N) / 64, 256, (2*64*65 + 2*64*64 + 64) * 4>>>((float*)d_out);
}

// round 2
// speedup vs baseline: 2.7742x; 2.7742x over previous
#include <cuda_runtime.h>
#include <math.h>

typedef unsigned long long ull;

#define DINL __device__ __forceinline__

DINL ull pk2(float lo, float hi) {
    ull r; asm("mov.b64 %0, {%1,%2};" : "=l"(r) : "f"(lo), "f"(hi)); return r;
}
DINL void upk2(ull v, float& lo, float& hi) {
    asm("mov.b64 {%0,%1}, %2;" : "=f"(lo), "=f"(hi) : "l"(v));
}
DINL ull ffma2(ull a, ull b, ull c) {
    ull d; asm("fma.rn.f32x2 %0, %1, %2, %3;" : "=l"(d) : "l"(a), "l"(b), "l"(c)); return d;
}
DINL float ex2f(float x) {
    float y; asm("ex2.approx.f32 %0, %1;" : "=f"(y) : "f"(x)); return y;
}
DINL float gelu_exact(float x) {
    return 0.5f * x * (1.0f + erff(x * 0.7071067811865476f));
}

constexpr int B  = 2;
constexpr int C  = 64;
constexpr int HW = 48;
constexpr int N  = 2304;   // 48*48
constexpr int H  = 8;      // heads
constexpr int D  = 8;      // head dim
constexpr int KH = 1152;   // keys per half (key-split 2)

// ---------------- scratch (device globals; no allocs allowed) ----------------
__device__ __align__(16) float g_dep_t[B * C * N];            // (b, c, n)  n = w*48 + h
__device__ __align__(16) float g_qkv[2][3][B * H * N * D];    // [stream][q,k,v] (b,h,n,d)
__device__ __align__(16) float g_pacc[2 * 2 * 2 * N * C];     // [(att*2+b)*2+half][n][c] unnormalized P·V
__device__ __align__(16) float g_psum[2 * 2 * 2 * H * N];     // [(att*2+b)*2+half][h][n]  sum of p
__device__ __align__(16) float g_wefft[2][C * C];             // effective weights, [att][k*64+o]
__device__ __align__(16) float g_beff[C];                     // effective bias

// ---------------- kernel 1: depth 1x1 conv + ReLU + bilinear x2 upsample ----------------
__global__ void k_depth(const float* __restrict__ depth,
                        const float* __restrict__ w_exp,
                        const float* __restrict__ b_exp) {
    int idx = blockIdx.x * 256 + threadIdx.x;   // 0 .. B*N-1
    if (idx >= B * N) return;
    int b = idx / N, n = idx % N;
    int w = n / HW, h = n % HW;

    float sy = h * 0.5f - 0.25f;
    float fy = floorf(sy);
    float wy1 = sy - fy, wy0 = 1.0f - wy1;
    int y0 = max((int)fy, 0), y1 = min((int)fy + 1, 23);

    float sx = w * 0.5f - 0.25f;
    float fx = floorf(sx);
    float wx1 = sx - fx, wx0 = 1.0f - wx1;
    int x0 = max((int)fx, 0), x1 = min((int)fx + 1, 23);

    const float* dp = depth + b * 576;
    float d00 = dp[y0 * 24 + x0], d01 = dp[y0 * 24 + x1];
    float d10 = dp[y1 * 24 + x0], d11 = dp[y1 * 24 + x1];
    float w00 = wy0 * wx0, w01 = wy0 * wx1, w10 = wy1 * wx0, w11 = wy1 * wx1;

    for (int c = 0; c < C; c++) {
        float we = w_exp[c], be = b_exp[c];
        float v = w00 * fmaxf(fmaf(we, d00, be), 0.f)
                + w01 * fmaxf(fmaf(we, d01, be), 0.f)
                + w10 * fmaxf(fmaf(we, d10, be), 0.f)
                + w11 * fmaxf(fmaf(we, d11, be), 0.f);
        g_dep_t[(b * C + c) * N + n] = v;
    }
}

// ---------------- kernel 2: fused QKV GEMMs (both streams) ----------------
__global__ void k_qkv(const float* __restrict__ rgb,
                      const float* __restrict__ wq0, const float* __restrict__ wk0, const float* __restrict__ wv0,
                      const float* __restrict__ wq1, const float* __restrict__ wk1, const float* __restrict__ wv1) {
    extern __shared__ float sm[];
    float* sX  = sm;                 // [c][h] stride 49
    float* sWt = sm + 64 * 49;       // [c][oc] stride 196

    int w = blockIdx.x, b = blockIdx.y, s = blockIdx.z;
    int tid = threadIdx.x;           // 288 threads

    for (int idx = tid; idx < 64 * 48; idx += 288) {
        int c = idx / 48, h = idx % 48;
        float v = (s == 0) ? rgb[(b * C + c) * N + h * HW + w]
                           : g_dep_t[(b * C + c) * N + w * HW + h];
        sX[c * 49 + h] = v;
    }
    const float* wq = s ? wq1 : wq0;
    const float* wk = s ? wk1 : wk0;
    const float* wv = s ? wv1 : wv0;
    for (int idx = tid; idx < 64 * 192; idx += 288) {
        int oc = idx / 64, c = idx % 64;
        int sel = oc >> 6, ocm = oc & 63;
        const float* wm = (sel == 0) ? wq : (sel == 1 ? wk : wv);
        sWt[c * 196 + oc] = wm[ocm * 64 + c];
    }
    __syncthreads();

    int nl = tid % 48;        // = h
    int g  = tid / 48;        // 0..5
    int oc0 = g * 32;

    ull acc[16];
#pragma unroll
    for (int j = 0; j < 16; j++) acc[j] = 0ull;

    for (int c = 0; c < 64; c++) {
        float xv = sX[c * 49 + nl];
        ull xp = pk2(xv, xv);
        const ulonglong2* w2 = (const ulonglong2*)(sWt + c * 196 + oc0);
#pragma unroll
        for (int j = 0; j < 8; j++) {
            ulonglong2 wv2 = w2[j];
            acc[2 * j]     = ffma2(xp, wv2.x, acc[2 * j]);
            acc[2 * j + 1] = ffma2(xp, wv2.y, acc[2 * j + 1]);
        }
    }

    int n = w * HW + nl;
#pragma unroll
    for (int j = 0; j < 16; j++) {
        int oc = oc0 + 2 * j;
        int mat = oc >> 6, ocm = oc & 63, hd = ocm >> 3, d = ocm & 7;
        float lo, hi; upk2(acc[j], lo, hi);
        *(float2*)&g_qkv[s][mat][((size_t)(b * H + hd) * N + n) * D + d] = make_float2(lo, hi);
    }
}

// ---------------- kernel 3: cross-attention v2 ----------------
// key-split (2 halves, 1152 keys each, smem 73.7KB -> 2 CTA/SM)
// 2 queries/thread, pair-interleaved K: one ffma2 feeds 2 key logits.
// grid: x = q-chunk (4, 576 q each), y = h + 8*half (16), z = att*2 + b (4). 256 blocks, 288 thr.
__global__ void __launch_bounds__(288, 2) k_attn() {
    extern __shared__ float sm[];
    ull*    sK = (ull*)sm;                    // 576 pairs * 8 ull (interleaved) = 36864 B
    float4* sV = (float4*)(sm + 9216);        // 1152 keys * 2 float4 = 36864 B

    int chunk = blockIdx.x;
    int h = blockIdx.y & 7, half = blockIdx.y >> 3;
    int z = blockIdx.z;                        // att*2+b
    int att = z >> 1, b = z & 1;
    int tid = threadIdx.x;

    const float* Kg = g_qkv[1 - att][1] + ((size_t)(b * H + h) * N + half * KH) * D;
    const float* Vg = g_qkv[1 - att][2] + ((size_t)(b * H + h) * N + half * KH) * D;

    // V straight copy: 1152 keys * 2 float4
    const float4* Vg4 = (const float4*)Vg;
    for (int i = tid; i < KH * 2; i += 288) sV[i] = Vg4[i];
    // K interleaved pairs: sK[j*8+d] = (K[2j][d], K[2j+1][d])
    const float4* Kg4 = (const float4*)Kg;
    for (int j = tid; j < KH / 2; j += 288) {
        float4 a0 = Kg4[4 * j], a1 = Kg4[4 * j + 1];
        float4 c0 = Kg4[4 * j + 2], c1 = Kg4[4 * j + 3];
        ull* d = sK + j * 8;
        d[0] = pk2(a0.x, c0.x); d[1] = pk2(a0.y, c0.y);
        d[2] = pk2(a0.z, c0.z); d[3] = pk2(a0.w, c0.w);
        d[4] = pk2(a1.x, c1.x); d[5] = pk2(a1.y, c1.y);
        d[6] = pk2(a1.z, c1.z); d[7] = pk2(a1.w, c1.w);
    }
    __syncthreads();

    int n0 = chunk * 576 + tid;
    int n1 = n0 + 288;
    const float* Qb = g_qkv[att][0] + (size_t)(b * H + h) * N * D;

    constexpr float QS = 0.3535533905932738f * 1.4426950408889634f; // scale * log2(e)
    constexpr float SHIFTF = -14.4269504088896f;                     // -10 * log2(e); cancels

    float4 qa = *(const float4*)(Qb + (size_t)n0 * D);
    float4 qb = *(const float4*)(Qb + (size_t)n0 * D + 4);
    float4 qc = *(const float4*)(Qb + (size_t)n1 * D);
    float4 qd = *(const float4*)(Qb + (size_t)n1 * D + 4);
    ull qp0[8], qp1[8];
    qp0[0] = pk2(qa.x * QS, qa.x * QS); qp0[1] = pk2(qa.y * QS, qa.y * QS);
    qp0[2] = pk2(qa.z * QS, qa.z * QS); qp0[3] = pk2(qa.w * QS, qa.w * QS);
    qp0[4] = pk2(qb.x * QS, qb.x * QS); qp0[5] = pk2(qb.y * QS, qb.y * QS);
    qp0[6] = pk2(qb.z * QS, qb.z * QS); qp0[7] = pk2(qb.w * QS, qb.w * QS);
    qp1[0] = pk2(qc.x * QS, qc.x * QS); qp1[1] = pk2(qc.y * QS, qc.y * QS);
    qp1[2] = pk2(qc.z * QS, qc.z * QS); qp1[3] = pk2(qc.w * QS, qc.w * QS);
    qp1[4] = pk2(qd.x * QS, qd.x * QS); qp1[5] = pk2(qd.y * QS, qd.y * QS);
    qp1[6] = pk2(qd.z * QS, qd.z * QS); qp1[7] = pk2(qd.w * QS, qd.w * QS);

    const ull SH2 = pk2(SHIFTF, SHIFTF);
    const ulonglong2* sK2 = (const ulonglong2*)sK;
    const ulonglong2* sV2 = (const ulonglong2*)sV;

    ull acc0[4] = {0, 0, 0, 0}, acc1[4] = {0, 0, 0, 0};
    float ss0a = 0.f, ss0b = 0.f, ss1a = 0.f, ss1b = 0.f;

#pragma unroll 2
    for (int j = 0; j < KH / 2; j++) {
        ulonglong2 kA = sK2[4 * j],     kB = sK2[4 * j + 1];
        ulonglong2 kC = sK2[4 * j + 2], kD = sK2[4 * j + 3];
        ull t0 = ffma2(qp0[0], kA.x, SH2);
        ull t1 = ffma2(qp1[0], kA.x, SH2);
        t0 = ffma2(qp0[1], kA.y, t0); t1 = ffma2(qp1[1], kA.y, t1);
        t0 = ffma2(qp0[2], kB.x, t0); t1 = ffma2(qp1[2], kB.x, t1);
        t0 = ffma2(qp0[3], kB.y, t0); t1 = ffma2(qp1[3], kB.y, t1);
        t0 = ffma2(qp0[4], kC.x, t0); t1 = ffma2(qp1[4], kC.x, t1);
        t0 = ffma2(qp0[5], kC.y, t0); t1 = ffma2(qp1[5], kC.y, t1);
        t0 = ffma2(qp0[6], kD.x, t0); t1 = ffma2(qp1[6], kD.x, t1);
        t0 = ffma2(qp0[7], kD.y, t0); t1 = ffma2(qp1[7], kD.y, t1);

        float s00, s01, s10, s11;
        upk2(t0, s00, s01); upk2(t1, s10, s11);
        float p00 = ex2f(s00), p01 = ex2f(s01);
        float p10 = ex2f(s10), p11 = ex2f(s11);
        ss0a += p00; ss0b += p01; ss1a += p10; ss1b += p11;
        ull pp00 = pk2(p00, p00), pp01 = pk2(p01, p01);
        ull pp10 = pk2(p10, p10), pp11 = pk2(p11, p11);

        ulonglong2 vA = sV2[4 * j],     vB = sV2[4 * j + 1];  // key 2j   d0-7
        ulonglong2 vC = sV2[4 * j + 2], vD = sV2[4 * j + 3];  // key 2j+1 d0-7
        acc0[0] = ffma2(pp00, vA.x, acc0[0]); acc0[1] = ffma2(pp00, vA.y, acc0[1]);
        acc0[2] = ffma2(pp00, vB.x, acc0[2]); acc0[3] = ffma2(pp00, vB.y, acc0[3]);
        acc0[0] = ffma2(pp01, vC.x, acc0[0]); acc0[1] = ffma2(pp01, vC.y, acc0[1]);
        acc0[2] = ffma2(pp01, vD.x, acc0[2]); acc0[3] = ffma2(pp01, vD.y, acc0[3]);
        acc1[0] = ffma2(pp10, vA.x, acc1[0]); acc1[1] = ffma2(pp10, vA.y, acc1[1]);
        acc1[2] = ffma2(pp10, vB.x, acc1[2]); acc1[3] = ffma2(pp10, vB.y, acc1[3]);
        acc1[0] = ffma2(pp11, vC.x, acc1[0]); acc1[1] = ffma2(pp11, vC.y, acc1[1]);
        acc1[2] = ffma2(pp11, vD.x, acc1[2]); acc1[3] = ffma2(pp11, vD.y, acc1[3]);
    }

    // store unnormalized partials (combined linearly in k_out)
    size_t pb0 = (((size_t)z * 2 + half) * N + n0) * C + h * D;
    size_t pb1 = (((size_t)z * 2 + half) * N + n1) * C + h * D;
    float4 f;
    upk2(acc0[0], f.x, f.y); upk2(acc0[1], f.z, f.w); *(float4*)&g_pacc[pb0]     = f;
    upk2(acc0[2], f.x, f.y); upk2(acc0[3], f.z, f.w); *(float4*)&g_pacc[pb0 + 4] = f;
    upk2(acc1[0], f.x, f.y); upk2(acc1[1], f.z, f.w); *(float4*)&g_pacc[pb1]     = f;
    upk2(acc1[2], f.x, f.y); upk2(acc1[3], f.z, f.w); *(float4*)&g_pacc[pb1 + 4] = f;
    size_t sb = (((size_t)z * 2 + half) * H + h) * N;
    g_psum[sb + n0] = ss0a + ss0b;
    g_psum[sb + n1] = ss1a + ss1b;
}

// ---------------- kernel 4: effective proj+compress weights (64 blocks, coalesced) ----------------
__global__ void k_weff(const float* __restrict__ wrp, const float* __restrict__ brp,
                       const float* __restrict__ wdp, const float* __restrict__ bdp,
                       const float* __restrict__ wcomp, const float* __restrict__ bcomp) {
    __shared__ float sWc[128];
    __shared__ float sRed[64];
    int o = blockIdx.x;
    int tid = threadIdx.x;   // 128
    sWc[tid] = wcomp[o * 128 + tid];
    __syncthreads();
    int att = tid >> 6, k = tid & 63;
    const float* wp = att ? wdp : wrp;
    float acc = 0.f;
#pragma unroll
    for (int c = 0; c < 64; c++)
        acc = fmaf(sWc[att * 64 + c], wp[c * 64 + k], acc);
    g_wefft[att][k * 64 + o] = acc;
    if (tid < 64) sRed[tid] = sWc[tid] * brp[tid] + sWc[64 + tid] * bdp[tid];
    __syncthreads();
    if (tid == 0) {
        float a = bcomp[o];
        for (int c = 0; c < 64; c++) a += sRed[c];
        g_beff[o] = a;
    }
}

// ---------------- kernel 5: combine partials + (proj+compress) GEMM + GELU ----------------
// 144 blocks x 32 rows, 256 threads
__global__ void k_out(float* __restrict__ out) {
    extern __shared__ float sm[];
    float* sA   = sm;            // [att][r][k] stride 65 -> 4160 floats
    float* sW   = sm + 4160;     // [att][k][o]          -> 8192 floats
    float* sInv = sm + 12352;    // [att][r][h]          -> 512 floats
    float* sB   = sm + 12864;    // 64 floats

    int tid = threadIdx.x;
    int row0 = blockIdx.x * 32;
    int bb = row0 / N;
    int nb = row0 - bb * N;

    // 1/(psum_half0 + psum_half1)
    for (int idx = tid; idx < 512; idx += 256) {
        int att = idx >> 8, r = (idx >> 3) & 31, hh = idx & 7;
        int n = nb + r;
        size_t base = ((size_t)(att * 2 + bb) * 2) * H * N + (size_t)hh * N + n;
        float s0 = g_psum[base];
        float s1 = g_psum[base + (size_t)H * N];
        sInv[(att * 32 + r) * 8 + hh] = 1.0f / (s0 + s1);
    }
    for (int idx = tid; idx < 2 * 64 * 64; idx += 256)
        sW[idx] = ((const float*)g_wefft)[idx];
    if (tid < 64) sB[tid] = g_beff[tid];
    __syncthreads();

    // combine pacc halves, normalize -> sA
    for (int idx = tid; idx < 1024; idx += 256) {
        int att = idx >> 9, r = (idx >> 4) & 31, c4 = idx & 15;
        int c = c4 * 4;
        size_t b0 = (((size_t)(att * 2 + bb) * 2 + 0) * N + nb + r) * C + c;
        size_t b1 = (((size_t)(att * 2 + bb) * 2 + 1) * N + nb + r) * C + c;
        float4 x = *(const float4*)&g_pacc[b0];
        float4 y = *(const float4*)&g_pacc[b1];
        float inv = sInv[(att * 32 + r) * 8 + (c >> 3)];
        float* dst = sA + (att * 32 + r) * 65 + c;
        dst[0] = (x.x + y.x) * inv; dst[1] = (x.y + y.y) * inv;
        dst[2] = (x.z + y.z) * inv; dst[3] = (x.w + y.w) * inv;
    }
    __syncthreads();

    int r = tid & 31, og = tid >> 5, o0 = og * 8;
    ull acc[4] = {0, 0, 0, 0};
    for (int k = 0; k < 64; k++) {
        float a0 = sA[(0 * 32 + r) * 65 + k];
        float a1 = sA[(1 * 32 + r) * 65 + k];
        ull pa0 = pk2(a0, a0), pa1 = pk2(a1, a1);
        const ulonglong2* w0 = (const ulonglong2*)(sW + (0 * 64 + k) * 64 + o0);
        const ulonglong2* w1 = (const ulonglong2*)(sW + (64 + k) * 64 + o0);
        ulonglong2 u0 = w0[0], u0b = w0[1], u1 = w1[0], u1b = w1[1];
        acc[0] = ffma2(pa0, u0.x,  acc[0]); acc[1] = ffma2(pa0, u0.y,  acc[1]);
        acc[2] = ffma2(pa0, u0b.x, acc[2]); acc[3] = ffma2(pa0, u0b.y, acc[3]);
        acc[0] = ffma2(pa1, u1.x,  acc[0]); acc[1] = ffma2(pa1, u1.y,  acc[1]);
        acc[2] = ffma2(pa1, u1b.x, acc[2]); acc[3] = ffma2(pa1, u1b.y, acc[3]);
    }

    int n = nb + r;
#pragma unroll
    for (int j = 0; j < 4; j++) {
        float lo, hi; upk2(acc[j], lo, hi);
        int o = o0 + 2 * j;
        out[((size_t)(bb * C + o)) * N + n]     = gelu_exact(lo + sB[o]);
        out[((size_t)(bb * C + o + 1)) * N + n] = gelu_exact(hi + sB[o + 1]);
    }
}

// ---------------- launch ----------------
extern "C" void kernel_launch(void* const* d_in, const int* in_sizes, int n_in,
                              void* d_out, int out_size) {
    const float* rgb    = (const float*)d_in[0];
    const float* depth  = (const float*)d_in[1];
    const float* w_exp  = (const float*)d_in[2];
    const float* b_exp  = (const float*)d_in[3];
    const float* wrq    = (const float*)d_in[4];
    const float* wrk    = (const float*)d_in[5];
    const float* wrv    = (const float*)d_in[6];
    const float* wdq    = (const float*)d_in[7];
    const float* wdk    = (const float*)d_in[8];
    const float* wdv    = (const float*)d_in[9];
    const float* wrp    = (const float*)d_in[10];
    const float* brp    = (const float*)d_in[11];
    const float* wdp    = (const float*)d_in[12];
    const float* bdp    = (const float*)d_in[13];
    const float* wcomp  = (const float*)d_in[14];
    const float* bcomp  = (const float*)d_in[15];

    const int QKV_SMEM  = (64 * 49 + 64 * 196) * 4;
    const int ATTN_SMEM = 2 * KH * D * 4;                  // 73728
    const int OUT_SMEM  = (4160 + 8192 + 512 + 64) * 4;    // 51712

    cudaFuncSetAttribute(k_qkv,  cudaFuncAttributeMaxDynamicSharedMemorySize, QKV_SMEM);
    cudaFuncSetAttribute(k_attn, cudaFuncAttributeMaxDynamicSharedMemorySize, ATTN_SMEM);
    cudaFuncSetAttribute(k_out,  cudaFuncAttributeMaxDynamicSharedMemorySize, OUT_SMEM);

    k_weff<<<64, 128>>>(wrp, brp, wdp, bdp, wcomp, bcomp);
    k_depth<<<(B * N + 255) / 256, 256>>>(depth, w_exp, b_exp);
    k_qkv<<<dim3(48, 2, 2), 288, QKV_SMEM>>>(rgb, wrq, wrk, wrv, wdq, wdk, wdv);
    k_attn<<<dim3(4, 16, 4), 288, ATTN_SMEM>>>();
    k_out<<<144, 256, OUT_SMEM>>>((float*)d_out);
}

// round 3
// speedup vs baseline: 2.8690x; 1.0342x over previous
#include <cuda_runtime.h>
#include <math.h>

typedef unsigned long long ull;

#define DINL __device__ __forceinline__

DINL ull pk2(float lo, float hi) {
    ull r; asm("mov.b64 %0, {%1,%2};" : "=l"(r) : "f"(lo), "f"(hi)); return r;
}
DINL void upk2(ull v, float& lo, float& hi) {
    asm("mov.b64 {%0,%1}, %2;" : "=f"(lo), "=f"(hi) : "l"(v));
}
DINL ull ffma2(ull a, ull b, ull c) {
    ull d; asm("fma.rn.f32x2 %0, %1, %2, %3;" : "=l"(d) : "l"(a), "l"(b), "l"(c)); return d;
}
DINL float ex2f(float x) {
    float y; asm("ex2.approx.f32 %0, %1;" : "=f"(y) : "f"(x)); return y;
}
DINL float gelu_exact(float x) {
    return 0.5f * x * (1.0f + erff(x * 0.7071067811865476f));
}

constexpr int B  = 2;
constexpr int C  = 64;
constexpr int HW = 48;
constexpr int N  = 2304;   // 48*48
constexpr int H  = 8;      // heads
constexpr int D  = 8;      // head dim
constexpr int KQ = 576;    // keys per quarter (key-split 4)

// ---------------- scratch (device globals; no allocs allowed) ----------------
__device__ __align__(16) float g_qkv[2][3][B * H * N * D];    // [stream][q,k,v] (b,h,n,d)
__device__ __align__(16) float g_pacc[4 * 4 * N * C];         // [z][quarter][n][c] unnormalized P·V
__device__ __align__(16) float g_psum[4 * 4 * H * N];         // [z][quarter][h][n]  sum of p
__device__ __align__(16) float g_wefft[2][C * C];             // effective weights, [att][k*64+o]
__device__ __align__(16) float g_beff[C];                     // effective bias

// ---------------- kernel 1: fused QKV GEMMs (both streams; depth path inlined) ----------------
// block = one (stream, b, w-column): 48 rows x 192 output channels, K=64
__global__ void k_qkv(const float* __restrict__ rgb,
                      const float* __restrict__ depth,
                      const float* __restrict__ w_exp,
                      const float* __restrict__ b_exp,
                      const float* __restrict__ wq0, const float* __restrict__ wk0, const float* __restrict__ wv0,
                      const float* __restrict__ wq1, const float* __restrict__ wk1, const float* __restrict__ wv1) {
    extern __shared__ float sm[];
    float* sX  = sm;                 // [c][h] stride 49
    float* sWt = sm + 64 * 49;       // [c][oc] stride 196

    int w = blockIdx.x, b = blockIdx.y, s = blockIdx.z;
    int tid = threadIdx.x;           // 288 threads

    if (s == 0) {
        for (int idx = tid; idx < 64 * 48; idx += 288) {
            int c = idx / 48, h = idx % 48;
            sX[c * 49 + h] = rgb[(b * C + c) * N + h * HW + w];
        }
    } else {
        // inline: depth 1x1 conv + ReLU + bilinear 2x upsample at (row=h, col=w)
        float sx = w * 0.5f - 0.25f;
        float fx = floorf(sx);
        float wx1 = sx - fx, wx0 = 1.0f - wx1;
        int x0 = max((int)fx, 0), x1 = min((int)fx + 1, 23);
        const float* dp = depth + b * 576;
        for (int idx = tid; idx < 64 * 48; idx += 288) {
            int c = idx / 48, h = idx % 48;
            float sy = h * 0.5f - 0.25f;
            float fy = floorf(sy);
            float wy1 = sy - fy, wy0 = 1.0f - wy1;
            int y0 = max((int)fy, 0), y1 = min((int)fy + 1, 23);
            float d00 = dp[y0 * 24 + x0], d01 = dp[y0 * 24 + x1];
            float d10 = dp[y1 * 24 + x0], d11 = dp[y1 * 24 + x1];
            float we = w_exp[c], be = b_exp[c];
            float v = wy0 * wx0 * fmaxf(fmaf(we, d00, be), 0.f)
                    + wy0 * wx1 * fmaxf(fmaf(we, d01, be), 0.f)
                    + wy1 * wx0 * fmaxf(fmaf(we, d10, be), 0.f)
                    + wy1 * wx1 * fmaxf(fmaf(we, d11, be), 0.f);
            sX[c * 49 + h] = v;
        }
    }
    const float* wq = s ? wq1 : wq0;
    const float* wk = s ? wk1 : wk0;
    const float* wv = s ? wv1 : wv0;
    for (int idx = tid; idx < 64 * 192; idx += 288) {
        int oc = idx / 64, c = idx % 64;
        int sel = oc >> 6, ocm = oc & 63;
        const float* wm = (sel == 0) ? wq : (sel == 1 ? wk : wv);
        sWt[c * 196 + oc] = wm[ocm * 64 + c];
    }
    __syncthreads();

    int nl = tid % 48;        // = h
    int g  = tid / 48;        // 0..5
    int oc0 = g * 32;

    ull acc[16];
#pragma unroll
    for (int j = 0; j < 16; j++) acc[j] = 0ull;

    for (int c = 0; c < 64; c++) {
        float xv = sX[c * 49 + nl];
        ull xp = pk2(xv, xv);
        const ulonglong2* w2 = (const ulonglong2*)(sWt + c * 196 + oc0);
#pragma unroll
        for (int j = 0; j < 8; j++) {
            ulonglong2 wv2 = w2[j];
            acc[2 * j]     = ffma2(xp, wv2.x, acc[2 * j]);
            acc[2 * j + 1] = ffma2(xp, wv2.y, acc[2 * j + 1]);
        }
    }

    int n = w * HW + nl;
#pragma unroll
    for (int j = 0; j < 16; j++) {
        int oc = oc0 + 2 * j;
        int mat = oc >> 6, ocm = oc & 63, hd = ocm >> 3, d = ocm & 7;
        float lo, hi; upk2(acc[j], lo, hi);
        *(float2*)&g_qkv[s][mat][((size_t)(b * H + hd) * N + n) * D + d] = make_float2(lo, hi);
    }
}

// ---------------- kernel 2: cross-attention v3 ----------------
// key-split 4 (576 keys/quarter, smem 36.9KB -> 4 CTA/SM), 1 query/thread.
// K pair-interleaved in smem: one ffma2 accumulates logits for 2 keys.
// grid: x = q-chunk (8, 288 q each), y = h + 8*quarter (32), z = att*2 + b (4). 1024 blocks.
__global__ void __launch_bounds__(288, 4) k_attn() {
    extern __shared__ float sm[];
    ull*    sK = (ull*)sm;                    // 288 pairs * 8 ull = 18432 B
    float4* sV = (float4*)(sm + 4608);        // 576 keys * 2 float4 = 18432 B

    int chunk = blockIdx.x;
    int h = blockIdx.y & 7, quarter = blockIdx.y >> 3;
    int z = blockIdx.z;                        // att*2+b
    int att = z >> 1, b = z & 1;
    int tid = threadIdx.x;

    const float* Kg = g_qkv[1 - att][1] + ((size_t)(b * H + h) * N + quarter * KQ) * D;
    const float* Vg = g_qkv[1 - att][2] + ((size_t)(b * H + h) * N + quarter * KQ) * D;

    // V straight copy: 576 keys * 2 float4
    const float4* Vg4 = (const float4*)Vg;
    for (int i = tid; i < KQ * 2; i += 288) sV[i] = Vg4[i];
    // K interleaved pairs: sK[j*8+d] = (K[2j][d], K[2j+1][d])
    const float4* Kg4 = (const float4*)Kg;
    {
        int j = tid;   // exactly 288 pairs
        float4 a0 = Kg4[4 * j], a1 = Kg4[4 * j + 1];
        float4 c0 = Kg4[4 * j + 2], c1 = Kg4[4 * j + 3];
        ull* d = sK + j * 8;
        d[0] = pk2(a0.x, c0.x); d[1] = pk2(a0.y, c0.y);
        d[2] = pk2(a0.z, c0.z); d[3] = pk2(a0.w, c0.w);
        d[4] = pk2(a1.x, c1.x); d[5] = pk2(a1.y, c1.y);
        d[6] = pk2(a1.z, c1.z); d[7] = pk2(a1.w, c1.w);
    }
    __syncthreads();

    int n = chunk * 288 + tid;
    const float* qp_g = g_qkv[att][0] + ((size_t)(b * H + h) * N + n) * D;

    constexpr float QS = 0.3535533905932738f * 1.4426950408889634f; // scale * log2(e)
    constexpr float SHIFTF = -14.4269504088896f;                     // cancels in normalization

    float4 qa = ((const float4*)qp_g)[0];
    float4 qb = ((const float4*)qp_g)[1];
    ull qp[8];
    qp[0] = pk2(qa.x * QS, qa.x * QS); qp[1] = pk2(qa.y * QS, qa.y * QS);
    qp[2] = pk2(qa.z * QS, qa.z * QS); qp[3] = pk2(qa.w * QS, qa.w * QS);
    qp[4] = pk2(qb.x * QS, qb.x * QS); qp[5] = pk2(qb.y * QS, qb.y * QS);
    qp[6] = pk2(qb.z * QS, qb.z * QS); qp[7] = pk2(qb.w * QS, qb.w * QS);

    const ull SH2 = pk2(SHIFTF, SHIFTF);
    const ulonglong2* sK2 = (const ulonglong2*)sK;
    const ulonglong2* sV2 = (const ulonglong2*)sV;

    ull acc[4] = {0, 0, 0, 0};
    float ss0 = 0.f, ss1 = 0.f;

#pragma unroll 4
    for (int j = 0; j < KQ / 2; j++) {
        ulonglong2 kA = sK2[4 * j],     kB = sK2[4 * j + 1];
        ulonglong2 kC = sK2[4 * j + 2], kD = sK2[4 * j + 3];
        ull t = ffma2(qp[0], kA.x, SH2);
        t = ffma2(qp[1], kA.y, t);
        t = ffma2(qp[2], kB.x, t);
        t = ffma2(qp[3], kB.y, t);
        t = ffma2(qp[4], kC.x, t);
        t = ffma2(qp[5], kC.y, t);
        t = ffma2(qp[6], kD.x, t);
        t = ffma2(qp[7], kD.y, t);

        float s0, s1;
        upk2(t, s0, s1);
        float p0 = ex2f(s0), p1 = ex2f(s1);
        ss0 += p0; ss1 += p1;
        ull pp0 = pk2(p0, p0), pp1 = pk2(p1, p1);

        ulonglong2 vA = sV2[4 * j],     vB = sV2[4 * j + 1];  // key 2j   d0-7
        ulonglong2 vC = sV2[4 * j + 2], vD = sV2[4 * j + 3];  // key 2j+1 d0-7
        acc[0] = ffma2(pp0, vA.x, acc[0]); acc[1] = ffma2(pp0, vA.y, acc[1]);
        acc[2] = ffma2(pp0, vB.x, acc[2]); acc[3] = ffma2(pp0, vB.y, acc[3]);
        acc[0] = ffma2(pp1, vC.x, acc[0]); acc[1] = ffma2(pp1, vC.y, acc[1]);
        acc[2] = ffma2(pp1, vD.x, acc[2]); acc[3] = ffma2(pp1, vD.y, acc[3]);
    }

    // store unnormalized partials (combined linearly in k_out)
    size_t pb = (((size_t)z * 4 + quarter) * N + n) * C + h * D;
    float4 f;
    upk2(acc[0], f.x, f.y); upk2(acc[1], f.z, f.w); *(float4*)&g_pacc[pb]     = f;
    upk2(acc[2], f.x, f.y); upk2(acc[3], f.z, f.w); *(float4*)&g_pacc[pb + 4] = f;
    g_psum[(((size_t)z * 4 + quarter) * H + h) * N + n] = ss0 + ss1;
}

// ---------------- kernel 3: effective proj+compress weights ----------------
__global__ void k_weff(const float* __restrict__ wrp, const float* __restrict__ brp,
                       const float* __restrict__ wdp, const float* __restrict__ bdp,
                       const float* __restrict__ wcomp, const float* __restrict__ bcomp) {
    __shared__ float sWc[128];
    __shared__ float sRed[64];
    int o = blockIdx.x;
    int tid = threadIdx.x;   // 128
    sWc[tid] = wcomp[o * 128 + tid];
    __syncthreads();
    int att = tid >> 6, k = tid & 63;
    const float* wp = att ? wdp : wrp;
    float acc = 0.f;
#pragma unroll
    for (int c = 0; c < 64; c++)
        acc = fmaf(sWc[att * 64 + c], wp[c * 64 + k], acc);
    g_wefft[att][k * 64 + o] = acc;
    if (tid < 64) sRed[tid] = sWc[tid] * brp[tid] + sWc[64 + tid] * bdp[tid];
    __syncthreads();
    if (tid == 0) {
        float a = bcomp[o];
        for (int c = 0; c < 64; c++) a += sRed[c];
        g_beff[o] = a;
    }
}

// ---------------- kernel 4: combine partials + (proj+compress) GEMM + GELU ----------------
// 144 blocks x 32 rows, 256 threads
__global__ void k_out(float* __restrict__ out) {
    extern __shared__ float sm[];
    float* sA   = sm;            // [att][r][k] stride 65 -> 4160 floats
    float* sW   = sm + 4160;     // [att][k][o]          -> 8192 floats
    float* sInv = sm + 12352;    // [att][r][h]          -> 512 floats
    float* sB   = sm + 12864;    // 64 floats

    int tid = threadIdx.x;
    int row0 = blockIdx.x * 32;
    int bb = row0 / N;
    int nb = row0 - bb * N;

    // 1/(sum over 4 quarters of psum)
    for (int idx = tid; idx < 512; idx += 256) {
        int att = idx >> 8, r = (idx >> 3) & 31, hh = idx & 7;
        int n = nb + r;
        int z = att * 2 + bb;
        float s = 0.f;
#pragma unroll
        for (int qq = 0; qq < 4; qq++)
            s += g_psum[(((size_t)z * 4 + qq) * H + hh) * N + n];
        sInv[(att * 32 + r) * 8 + hh] = 1.0f / s;
    }
    for (int idx = tid; idx < 2 * 64 * 64; idx += 256)
        sW[idx] = ((const float*)g_wefft)[idx];
    if (tid < 64) sB[tid] = g_beff[tid];
    __syncthreads();

    // combine pacc quarters, normalize -> sA
    for (int idx = tid; idx < 1024; idx += 256) {
        int att = idx >> 9, r = (idx >> 4) & 31, c4 = idx & 15;
        int c = c4 * 4;
        int z = att * 2 + bb;
        float4 x = make_float4(0.f, 0.f, 0.f, 0.f);
#pragma unroll
        for (int qq = 0; qq < 4; qq++) {
            float4 y = *(const float4*)&g_pacc[(((size_t)z * 4 + qq) * N + nb + r) * C + c];
            x.x += y.x; x.y += y.y; x.z += y.z; x.w += y.w;
        }
        float inv = sInv[(att * 32 + r) * 8 + (c >> 3)];
        float* dst = sA + (att * 32 + r) * 65 + c;
        dst[0] = x.x * inv; dst[1] = x.y * inv;
        dst[2] = x.z * inv; dst[3] = x.w * inv;
    }
    __syncthreads();

    int r = tid & 31, og = tid >> 5, o0 = og * 8;
    ull acc[4] = {0, 0, 0, 0};
    for (int k = 0; k < 64; k++) {
        float a0 = sA[(0 * 32 + r) * 65 + k];
        float a1 = sA[(1 * 32 + r) * 65 + k];
        ull pa0 = pk2(a0, a0), pa1 = pk2(a1, a1);
        const ulonglong2* w0 = (const ulonglong2*)(sW + (0 * 64 + k) * 64 + o0);
        const ulonglong2* w1 = (const ulonglong2*)(sW + (64 + k) * 64 + o0);
        ulonglong2 u0 = w0[0], u0b = w0[1], u1 = w1[0], u1b = w1[1];
        acc[0] = ffma2(pa0, u0.x,  acc[0]); acc[1] = ffma2(pa0, u0.y,  acc[1]);
        acc[2] = ffma2(pa0, u0b.x, acc[2]); acc[3] = ffma2(pa0, u0b.y, acc[3]);
        acc[0] = ffma2(pa1, u1.x,  acc[0]); acc[1] = ffma2(pa1, u1.y,  acc[1]);
        acc[2] = ffma2(pa1, u1b.x, acc[2]); acc[3] = ffma2(pa1, u1b.y, acc[3]);
    }

    int n = nb + r;
#pragma unroll
    for (int j = 0; j < 4; j++) {
        float lo, hi; upk2(acc[j], lo, hi);
        int o = o0 + 2 * j;
        out[((size_t)(bb * C + o)) * N + n]     = gelu_exact(lo + sB[o]);
        out[((size_t)(bb * C + o + 1)) * N + n] = gelu_exact(hi + sB[o + 1]);
    }
}

// ---------------- launch ----------------
extern "C" void kernel_launch(void* const* d_in, const int* in_sizes, int n_in,
                              void* d_out, int out_size) {
    const float* rgb    = (const float*)d_in[0];
    const float* depth  = (const float*)d_in[1];
    const float* w_exp  = (const float*)d_in[2];
    const float* b_exp  = (const float*)d_in[3];
    const float* wrq    = (const float*)d_in[4];
    const float* wrk    = (const float*)d_in[5];
    const float* wrv    = (const float*)d_in[6];
    const float* wdq    = (const float*)d_in[7];
    const float* wdk    = (const float*)d_in[8];
    const float* wdv    = (const float*)d_in[9];
    const float* wrp    = (const float*)d_in[10];
    const float* brp    = (const float*)d_in[11];
    const float* wdp    = (const float*)d_in[12];
    const float* bdp    = (const float*)d_in[13];
    const float* wcomp  = (const float*)d_in[14];
    const float* bcomp  = (const float*)d_in[15];

    const int QKV_SMEM  = (64 * 49 + 64 * 196) * 4;        // 62720
    const int ATTN_SMEM = 2 * KQ * D * 4;                  // 36864
    const int OUT_SMEM  = (4160 + 8192 + 512 + 64) * 4;    // 51712

    cudaFuncSetAttribute(k_qkv,  cudaFuncAttributeMaxDynamicSharedMemorySize, QKV_SMEM);
    cudaFuncSetAttribute(k_attn, cudaFuncAttributeMaxDynamicSharedMemorySize, ATTN_SMEM);
    cudaFuncSetAttribute(k_out,  cudaFuncAttributeMaxDynamicSharedMemorySize, OUT_SMEM);

    k_weff<<<64, 128>>>(wrp, brp, wdp, bdp, wcomp, bcomp);
    k_qkv<<<dim3(48, 2, 2), 288, QKV_SMEM>>>(rgb, depth, w_exp, b_exp,
                                             wrq, wrk, wrv, wdq, wdk, wdv);
    k_attn<<<dim3(8, 32, 4), 288, ATTN_SMEM>>>();
    k_out<<<144, 256, OUT_SMEM>>>((float*)d_out);
}

// round 4
// speedup vs baseline: 3.2512x; 1.1332x over previous
#include <cuda_runtime.h>
#include <math.h>

typedef unsigned long long ull;

#define DINL __device__ __forceinline__

DINL ull pk2(float lo, float hi) {
    ull r; asm("mov.b64 %0, {%1,%2};" : "=l"(r) : "f"(lo), "f"(hi)); return r;
}
DINL void upk2(ull v, float& lo, float& hi) {
    asm("mov.b64 {%0,%1}, %2;" : "=f"(lo), "=f"(hi) : "l"(v));
}
DINL ull ffma2(ull a, ull b, ull c) {
    ull d; asm("fma.rn.f32x2 %0, %1, %2, %3;" : "=l"(d) : "l"(a), "l"(b), "l"(c)); return d;
}
DINL float ex2f(float x) {
    float y; asm("ex2.approx.f32 %0, %1;" : "=f"(y) : "f"(x)); return y;
}
DINL float gelu_exact(float x) {
    return 0.5f * x * (1.0f + erff(x * 0.7071067811865476f));
}

constexpr int B  = 2;
constexpr int C  = 64;
constexpr int HW = 48;
constexpr int N  = 2304;   // 48*48
constexpr int H  = 8;      // heads
constexpr int D  = 8;      // head dim
constexpr int KQ = 576;    // keys per quarter (key-split 4)

// ---------------- scratch (device globals; no allocs allowed) ----------------
__device__ __align__(16) float g_qkv[2][3][B * H * N * D];    // [stream][q,k,v] (b,h,n,d)
__device__ __align__(16) float g_pacc[4 * 4 * N * C];         // [z][quarter][n][c] unnormalized P·V
__device__ __align__(16) float g_psum[4 * 4 * H * N];         // [z][quarter][h][n]  sum of p
__device__ __align__(16) float g_wefft[2][C * C];             // effective weights, [att][k*64+o]
__device__ __align__(16) float g_beff[C];                     // effective bias

// ---------------- kernel 1: fused QKV GEMMs (both streams; depth path inlined) ----------------
__global__ void k_qkv(const float* __restrict__ rgb,
                      const float* __restrict__ depth,
                      const float* __restrict__ w_exp,
                      const float* __restrict__ b_exp,
                      const float* __restrict__ wq0, const float* __restrict__ wk0, const float* __restrict__ wv0,
                      const float* __restrict__ wq1, const float* __restrict__ wk1, const float* __restrict__ wv1) {
    extern __shared__ float sm[];
    float* sX  = sm;                 // [c][h] stride 49
    float* sWt = sm + 64 * 49;       // [c][oc] stride 196

    int w = blockIdx.x, b = blockIdx.y, s = blockIdx.z;
    int tid = threadIdx.x;           // 288 threads

    if (s == 0) {
        for (int idx = tid; idx < 64 * 48; idx += 288) {
            int c = idx / 48, h = idx % 48;
            sX[c * 49 + h] = rgb[(b * C + c) * N + h * HW + w];
        }
    } else {
        float sx = w * 0.5f - 0.25f;
        float fx = floorf(sx);
        float wx1 = sx - fx, wx0 = 1.0f - wx1;
        int x0 = max((int)fx, 0), x1 = min((int)fx + 1, 23);
        const float* dp = depth + b * 576;
        for (int idx = tid; idx < 64 * 48; idx += 288) {
            int c = idx / 48, h = idx % 48;
            float sy = h * 0.5f - 0.25f;
            float fy = floorf(sy);
            float wy1 = sy - fy, wy0 = 1.0f - wy1;
            int y0 = max((int)fy, 0), y1 = min((int)fy + 1, 23);
            float d00 = dp[y0 * 24 + x0], d01 = dp[y0 * 24 + x1];
            float d10 = dp[y1 * 24 + x0], d11 = dp[y1 * 24 + x1];
            float we = w_exp[c], be = b_exp[c];
            float v = wy0 * wx0 * fmaxf(fmaf(we, d00, be), 0.f)
                    + wy0 * wx1 * fmaxf(fmaf(we, d01, be), 0.f)
                    + wy1 * wx0 * fmaxf(fmaf(we, d10, be), 0.f)
                    + wy1 * wx1 * fmaxf(fmaf(we, d11, be), 0.f);
            sX[c * 49 + h] = v;
        }
    }
    const float* wq = s ? wq1 : wq0;
    const float* wk = s ? wk1 : wk0;
    const float* wv = s ? wv1 : wv0;
    for (int idx = tid; idx < 64 * 192; idx += 288) {
        int oc = idx / 64, c = idx % 64;
        int sel = oc >> 6, ocm = oc & 63;
        const float* wm = (sel == 0) ? wq : (sel == 1 ? wk : wv);
        sWt[c * 196 + oc] = wm[ocm * 64 + c];
    }
    __syncthreads();

    int nl = tid % 48;        // = h
    int g  = tid / 48;        // 0..5
    int oc0 = g * 32;

    ull acc[16];
#pragma unroll
    for (int j = 0; j < 16; j++) acc[j] = 0ull;

    for (int c = 0; c < 64; c++) {
        float xv = sX[c * 49 + nl];
        ull xp = pk2(xv, xv);
        const ulonglong2* w2 = (const ulonglong2*)(sWt + c * 196 + oc0);
#pragma unroll
        for (int j = 0; j < 8; j++) {
            ulonglong2 wv2 = w2[j];
            acc[2 * j]     = ffma2(xp, wv2.x, acc[2 * j]);
            acc[2 * j + 1] = ffma2(xp, wv2.y, acc[2 * j + 1]);
        }
    }

    int n = w * HW + nl;
#pragma unroll
    for (int j = 0; j < 16; j++) {
        int oc = oc0 + 2 * j;
        int mat = oc >> 6, ocm = oc & 63, hd = ocm >> 3, d = ocm & 7;
        float lo, hi; upk2(acc[j], lo, hi);
        *(float2*)&g_qkv[s][mat][((size_t)(b * H + hd) * N + n) * D + d] = make_float2(lo, hi);
    }
}

// ---------------- kernel 2: cross-attention v5 ----------------
// key-split 4 (576 keys/quarter, smem 36.9KB), 128-thread CTAs, 6 CTA/SM,
// 2 queries/thread, pair-interleaved K (one ffma2 = 2 key logits).
// grid: x = q-chunk (9, 256 q each), y = h + 8*quarter (32), z = att*2 + b (4). 1152 blocks.
__global__ void __launch_bounds__(128, 6) k_attn() {
    extern __shared__ float sm[];
    ull*    sK = (ull*)sm;                    // 288 pairs * 8 ull = 18432 B
    float4* sV = (float4*)(sm + 4608);        // 576 keys * 2 float4 = 18432 B

    int chunk = blockIdx.x;
    int h = blockIdx.y & 7, quarter = blockIdx.y >> 3;
    int z = blockIdx.z;                        // att*2+b
    int att = z >> 1, b = z & 1;
    int tid = threadIdx.x;

    const float* Kg = g_qkv[1 - att][1] + ((size_t)(b * H + h) * N + quarter * KQ) * D;
    const float* Vg = g_qkv[1 - att][2] + ((size_t)(b * H + h) * N + quarter * KQ) * D;

    const float4* Vg4 = (const float4*)Vg;
    for (int i = tid; i < KQ * 2; i += 128) sV[i] = Vg4[i];
    const float4* Kg4 = (const float4*)Kg;
    for (int j = tid; j < KQ / 2; j += 128) {
        float4 a0 = Kg4[4 * j], a1 = Kg4[4 * j + 1];
        float4 c0 = Kg4[4 * j + 2], c1 = Kg4[4 * j + 3];
        ull* d = sK + j * 8;
        d[0] = pk2(a0.x, c0.x); d[1] = pk2(a0.y, c0.y);
        d[2] = pk2(a0.z, c0.z); d[3] = pk2(a0.w, c0.w);
        d[4] = pk2(a1.x, c1.x); d[5] = pk2(a1.y, c1.y);
        d[6] = pk2(a1.z, c1.z); d[7] = pk2(a1.w, c1.w);
    }
    __syncthreads();

    int n0 = chunk * 256 + tid;
    int n1 = n0 + 128;
    const float* Qb = g_qkv[att][0] + (size_t)(b * H + h) * N * D;

    constexpr float QS = 0.3535533905932738f * 1.4426950408889634f; // scale * log2(e)
    constexpr float SHIFTF = -14.4269504088896f;                     // cancels in normalization

    float4 qa = *(const float4*)(Qb + (size_t)n0 * D);
    float4 qb = *(const float4*)(Qb + (size_t)n0 * D + 4);
    float4 qc = *(const float4*)(Qb + (size_t)n1 * D);
    float4 qd = *(const float4*)(Qb + (size_t)n1 * D + 4);
    ull qp0[8], qp1[8];
    qp0[0] = pk2(qa.x * QS, qa.x * QS); qp0[1] = pk2(qa.y * QS, qa.y * QS);
    qp0[2] = pk2(qa.z * QS, qa.z * QS); qp0[3] = pk2(qa.w * QS, qa.w * QS);
    qp0[4] = pk2(qb.x * QS, qb.x * QS); qp0[5] = pk2(qb.y * QS, qb.y * QS);
    qp0[6] = pk2(qb.z * QS, qb.z * QS); qp0[7] = pk2(qb.w * QS, qb.w * QS);
    qp1[0] = pk2(qc.x * QS, qc.x * QS); qp1[1] = pk2(qc.y * QS, qc.y * QS);
    qp1[2] = pk2(qc.z * QS, qc.z * QS); qp1[3] = pk2(qc.w * QS, qc.w * QS);
    qp1[4] = pk2(qd.x * QS, qd.x * QS); qp1[5] = pk2(qd.y * QS, qd.y * QS);
    qp1[6] = pk2(qd.z * QS, qd.z * QS); qp1[7] = pk2(qd.w * QS, qd.w * QS);

    const ull SH2 = pk2(SHIFTF, SHIFTF);
    const ulonglong2* sK2 = (const ulonglong2*)sK;
    const ulonglong2* sV2 = (const ulonglong2*)sV;

    ull acc0[4] = {0, 0, 0, 0}, acc1[4] = {0, 0, 0, 0};
    float ss0 = 0.f, ss1 = 0.f;

#pragma unroll 2
    for (int j = 0; j < KQ / 2; j++) {
        ulonglong2 kA = sK2[4 * j],     kB = sK2[4 * j + 1];
        ulonglong2 kC = sK2[4 * j + 2], kD = sK2[4 * j + 3];
        ull t0 = ffma2(qp0[0], kA.x, SH2);
        ull t1 = ffma2(qp1[0], kA.x, SH2);
        t0 = ffma2(qp0[1], kA.y, t0); t1 = ffma2(qp1[1], kA.y, t1);
        t0 = ffma2(qp0[2], kB.x, t0); t1 = ffma2(qp1[2], kB.x, t1);
        t0 = ffma2(qp0[3], kB.y, t0); t1 = ffma2(qp1[3], kB.y, t1);
        t0 = ffma2(qp0[4], kC.x, t0); t1 = ffma2(qp1[4], kC.x, t1);
        t0 = ffma2(qp0[5], kC.y, t0); t1 = ffma2(qp1[5], kC.y, t1);
        t0 = ffma2(qp0[6], kD.x, t0); t1 = ffma2(qp1[6], kD.x, t1);
        t0 = ffma2(qp0[7], kD.y, t0); t1 = ffma2(qp1[7], kD.y, t1);

        float s00, s01, s10, s11;
        upk2(t0, s00, s01); upk2(t1, s10, s11);
        float p00 = ex2f(s00), p01 = ex2f(s01);
        float p10 = ex2f(s10), p11 = ex2f(s11);
        ss0 += p00 + p01; ss1 += p10 + p11;
        ull pp00 = pk2(p00, p00), pp01 = pk2(p01, p01);
        ull pp10 = pk2(p10, p10), pp11 = pk2(p11, p11);

        ulonglong2 vA = sV2[4 * j],     vB = sV2[4 * j + 1];  // key 2j   d0-7
        ulonglong2 vC = sV2[4 * j + 2], vD = sV2[4 * j + 3];  // key 2j+1 d0-7
        acc0[0] = ffma2(pp00, vA.x, acc0[0]); acc0[1] = ffma2(pp00, vA.y, acc0[1]);
        acc0[2] = ffma2(pp00, vB.x, acc0[2]); acc0[3] = ffma2(pp00, vB.y, acc0[3]);
        acc0[0] = ffma2(pp01, vC.x, acc0[0]); acc0[1] = ffma2(pp01, vC.y, acc0[1]);
        acc0[2] = ffma2(pp01, vD.x, acc0[2]); acc0[3] = ffma2(pp01, vD.y, acc0[3]);
        acc1[0] = ffma2(pp10, vA.x, acc1[0]); acc1[1] = ffma2(pp10, vA.y, acc1[1]);
        acc1[2] = ffma2(pp10, vB.x, acc1[2]); acc1[3] = ffma2(pp10, vB.y, acc1[3]);
        acc1[0] = ffma2(pp11, vC.x, acc1[0]); acc1[1] = ffma2(pp11, vC.y, acc1[1]);
        acc1[2] = ffma2(pp11, vD.x, acc1[2]); acc1[3] = ffma2(pp11, vD.y, acc1[3]);
    }

    // store unnormalized partials (combined linearly in k_out)
    size_t pb0 = (((size_t)z * 4 + quarter) * N + n0) * C + h * D;
    size_t pb1 = (((size_t)z * 4 + quarter) * N + n1) * C + h * D;
    float4 f;
    upk2(acc0[0], f.x, f.y); upk2(acc0[1], f.z, f.w); *(float4*)&g_pacc[pb0]     = f;
    upk2(acc0[2], f.x, f.y); upk2(acc0[3], f.z, f.w); *(float4*)&g_pacc[pb0 + 4] = f;
    upk2(acc1[0], f.x, f.y); upk2(acc1[1], f.z, f.w); *(float4*)&g_pacc[pb1]     = f;
    upk2(acc1[2], f.x, f.y); upk2(acc1[3], f.z, f.w); *(float4*)&g_pacc[pb1 + 4] = f;
    size_t sb = (((size_t)z * 4 + quarter) * H + h) * N;
    g_psum[sb + n0] = ss0;
    g_psum[sb + n1] = ss1;
}

// ---------------- kernel 3: effective proj+compress weights ----------------
__global__ void k_weff(const float* __restrict__ wrp, const float* __restrict__ brp,
                       const float* __restrict__ wdp, const float* __restrict__ bdp,
                       const float* __restrict__ wcomp, const float* __restrict__ bcomp) {
    __shared__ float sWc[128];
    __shared__ float sRed[64];
    int o = blockIdx.x;
    int tid = threadIdx.x;   // 128
    sWc[tid] = wcomp[o * 128 + tid];
    __syncthreads();
    int att = tid >> 6, k = tid & 63;
    const float* wp = att ? wdp : wrp;
    float acc = 0.f;
#pragma unroll
    for (int c = 0; c < 64; c++)
        acc = fmaf(sWc[att * 64 + c], wp[c * 64 + k], acc);
    g_wefft[att][k * 64 + o] = acc;
    if (tid < 64) sRed[tid] = sWc[tid] * brp[tid] + sWc[64 + tid] * bdp[tid];
    __syncthreads();
    if (tid == 0) {
        float a = bcomp[o];
        for (int c = 0; c < 64; c++) a += sRed[c];
        g_beff[o] = a;
    }
}

// ---------------- kernel 4: combine partials + (proj+compress) GEMM + GELU ----------------
// 288 blocks x 16 rows, 256 threads
__global__ void k_out(float* __restrict__ out) {
    extern __shared__ float sm[];
    float* sA   = sm;            // [att][r][k] stride 65 -> 2080 floats
    float* sW   = sm + 2080;     // [att][k][o]          -> 8192 floats
    float* sInv = sm + 10272;    // [att][r][h]          -> 256 floats
    float* sB   = sm + 10528;    // 64 floats

    int tid = threadIdx.x;
    int row0 = blockIdx.x * 16;
    int bb = row0 / N;
    int nb = row0 - bb * N;

    // 1/(sum over 4 quarters of psum)
    if (tid < 256) {
        int idx = tid;
        int att = idx >> 7, r = (idx >> 3) & 15, hh = idx & 7;
        int n = nb + r;
        int z = att * 2 + bb;
        float s = 0.f;
#pragma unroll
        for (int qq = 0; qq < 4; qq++)
            s += g_psum[(((size_t)z * 4 + qq) * H + hh) * N + n];
        sInv[(att * 16 + r) * 8 + hh] = 1.0f / s;
    }
    for (int idx = tid; idx < 2 * 64 * 64; idx += 256)
        sW[idx] = ((const float*)g_wefft)[idx];
    if (tid < 64) sB[tid] = g_beff[tid];
    __syncthreads();

    // combine pacc quarters, normalize -> sA
    for (int idx = tid; idx < 512; idx += 256) {
        int att = idx >> 8, r = (idx >> 4) & 15, c4 = idx & 15;
        int c = c4 * 4;
        int z = att * 2 + bb;
        float4 x = make_float4(0.f, 0.f, 0.f, 0.f);
#pragma unroll
        for (int qq = 0; qq < 4; qq++) {
            float4 y = *(const float4*)&g_pacc[(((size_t)z * 4 + qq) * N + nb + r) * C + c];
            x.x += y.x; x.y += y.y; x.z += y.z; x.w += y.w;
        }
        float inv = sInv[(att * 16 + r) * 8 + (c >> 3)];
        float* dst = sA + (att * 16 + r) * 65 + c;
        dst[0] = x.x * inv; dst[1] = x.y * inv;
        dst[2] = x.z * inv; dst[3] = x.w * inv;
    }
    __syncthreads();

    int r = tid & 15, og = tid >> 4, o0 = og * 4;
    ull acc[2] = {0, 0};
    for (int k = 0; k < 64; k++) {
        float a0 = sA[(0 * 16 + r) * 65 + k];
        float a1 = sA[(1 * 16 + r) * 65 + k];
        ull pa0 = pk2(a0, a0), pa1 = pk2(a1, a1);
        const ulonglong2* w0 = (const ulonglong2*)(sW + (0 * 64 + k) * 64 + o0);
        const ulonglong2* w1 = (const ulonglong2*)(sW + (64 + k) * 64 + o0);
        ulonglong2 u0 = w0[0], u1 = w1[0];
        acc[0] = ffma2(pa0, u0.x, acc[0]); acc[1] = ffma2(pa0, u0.y, acc[1]);
        acc[0] = ffma2(pa1, u1.x, acc[0]); acc[1] = ffma2(pa1, u1.y, acc[1]);
    }

    int n = nb + r;
#pragma unroll
    for (int j = 0; j < 2; j++) {
        float lo, hi; upk2(acc[j], lo, hi);
        int o = o0 + 2 * j;
        out[((size_t)(bb * C + o)) * N + n]     = gelu_exact(lo + sB[o]);
        out[((size_t)(bb * C + o + 1)) * N + n] = gelu_exact(hi + sB[o + 1]);
    }
}

// ---------------- launch ----------------
extern "C" void kernel_launch(void* const* d_in, const int* in_sizes, int n_in,
                              void* d_out, int out_size) {
    const float* rgb    = (const float*)d_in[0];
    const float* depth  = (const float*)d_in[1];
    const float* w_exp  = (const float*)d_in[2];
    const float* b_exp  = (const float*)d_in[3];
    const float* wrq    = (const float*)d_in[4];
    const float* wrk    = (const float*)d_in[5];
    const float* wrv    = (const float*)d_in[6];
    const float* wdq    = (const float*)d_in[7];
    const float* wdk    = (const float*)d_in[8];
    const float* wdv    = (const float*)d_in[9];
    const float* wrp    = (const float*)d_in[10];
    const float* brp    = (const float*)d_in[11];
    const float* wdp    = (const float*)d_in[12];
    const float* bdp    = (const float*)d_in[13];
    const float* wcomp  = (const float*)d_in[14];
    const float* bcomp  = (const float*)d_in[15];

    const int QKV_SMEM  = (64 * 49 + 64 * 196) * 4;        // 62720
    const int ATTN_SMEM = 2 * KQ * D * 4;                  // 36864
    const int OUT_SMEM  = (2080 + 8192 + 256 + 64) * 4;    // 42368

    cudaFuncSetAttribute(k_qkv,  cudaFuncAttributeMaxDynamicSharedMemorySize, QKV_SMEM);
    cudaFuncSetAttribute(k_attn, cudaFuncAttributeMaxDynamicSharedMemorySize, ATTN_SMEM);
    cudaFuncSetAttribute(k_out,  cudaFuncAttributeMaxDynamicSharedMemorySize, OUT_SMEM);

    k_weff<<<64, 128>>>(wrp, brp, wdp, bdp, wcomp, bcomp);
    k_qkv<<<dim3(48, 2, 2), 288, QKV_SMEM>>>(rgb, depth, w_exp, b_exp,
                                             wrq, wrk, wrv, wdq, wdk, wdv);
    k_attn<<<dim3(9, 32, 4), 128, ATTN_SMEM>>>();
    k_out<<<288, 256, OUT_SMEM>>>((float*)d_out);
}